// round 4
// baseline (speedup 1.0000x reference)
#include <cuda_runtime.h>

#define B_ROWS 8192
#define N_COLS 4096
#define THREADS 256
#define CPT 16  // columns per thread (4096 / 256)

// Global accumulators (device globals: no allocation allowed).
__device__ double g_sum_log2;
__device__ double g_sum_out;

__global__ __launch_bounds__(1) void init_kernel() {
    g_sum_log2 = 0.0;
    g_sum_out  = 0.0;
}

__global__ __launch_bounds__(THREADS)
void listmle_kernel(const float* __restrict__ outputs,
                    const int* __restrict__ labels) {
    __shared__ float srow[N_COLS];   // 16 KB: the row, original order
    __shared__ float s_w[8];         // warp scan sums
    __shared__ float s_r1[8];        // reduce: log2 sums
    __shared__ float s_r2[8];        // reduce: output sums

    const int row  = blockIdx.x;
    const int tid  = threadIdx.x;
    const int lane = tid & 31;
    const int wid  = tid >> 5;

    // ---- Phase 0: coalesced row load -> smem, and sum(outputs) on the fly.
    const float4* rowp = (const float4*)(outputs + (size_t)row * N_COLS);
    float4* srow4 = (float4*)srow;
    float sum_out = 0.0f;
#pragma unroll
    for (int k = 0; k < 4; k++) {
        float4 v = rowp[tid + k * THREADS];
        srow4[tid + k * THREADS] = v;
        sum_out += (v.x + v.y) + (v.z + v.w);
    }
    __syncthreads();

    // ---- Phase 1: gather own contiguous chunk via labels (int32), exp() into regs.
    const int4* lab = (const int4*)(labels + (size_t)row * N_COLS + tid * CPT);
    float e[CPT];
    float lsum = 0.0f;
#pragma unroll
    for (int j = 0; j < CPT / 4; j++) {
        int4 L = lab[j];                 // 4 consecutive labels
        float e0 = __expf(srow[L.x]);
        float e1 = __expf(srow[L.y]);
        float e2 = __expf(srow[L.z]);
        float e3 = __expf(srow[L.w]);
        e[4 * j]     = e0;
        e[4 * j + 1] = e1;
        e[4 * j + 2] = e2;
        e[4 * j + 3] = e3;
        lsum += (e0 + e1) + (e2 + e3);
    }

    // ---- Phase 2: block exclusive scan of the 256 chunk sums.
    float v = lsum;
#pragma unroll
    for (int off = 1; off < 32; off <<= 1) {
        float n = __shfl_up_sync(0xFFFFFFFFu, v, off);
        if (lane >= off) v += n;
    }
    if (lane == 31) s_w[wid] = v;       // warp totals (inclusive)
    __syncthreads();
    if (tid < 8) {
        float w = s_w[tid];
#pragma unroll
        for (int off = 1; off < 8; off <<= 1) {
            float n = __shfl_up_sync(0x000000FFu, w, off);
            if (tid >= off) w += n;
        }
        s_w[tid] = w;                   // inclusive scan of warp totals
    }
    __syncthreads();
    const float offset = (v - lsum) + (wid ? s_w[wid - 1] : 0.0f);

    // ---- Phase 3: running cumsum + sum-of-logs via product with exponent strip.
    // sum_j log2(c_j) accumulated exactly in the integer exponent + one final log2.
    float c = offset;
    float P = 1.0f;
    int   etot = 0;
#pragma unroll
    for (int j = 0; j < CPT; j++) {
        c += e[j];                       // inclusive prefix: cumsum of exp
        P *= c;                          // mantissa stripped each step -> no overflow
        int ib = __float_as_int(P);      // P > 0 always
        etot += ib >> 23;                // raw biased exponent
        P = __int_as_float((ib & 0x007FFFFF) | 0x3F800000);  // strip to mantissa
    }
    float tlog2 = (float)(etot - CPT * 127) + __log2f(P);

    // ---- Phase 4: block reduce (tlog2, sum_out), then double atomics.
#pragma unroll
    for (int off = 16; off; off >>= 1) {
        tlog2   += __shfl_down_sync(0xFFFFFFFFu, tlog2, off);
        sum_out += __shfl_down_sync(0xFFFFFFFFu, sum_out, off);
    }
    if (lane == 0) { s_r1[wid] = tlog2; s_r2[wid] = sum_out; }
    __syncthreads();
    if (tid == 0) {
        float a = 0.0f, b = 0.0f;
#pragma unroll
        for (int i = 0; i < 8; i++) { a += s_r1[i]; b += s_r2[i]; }
        atomicAdd(&g_sum_log2, (double)a);
        atomicAdd(&g_sum_out,  (double)b);
    }
}

__global__ __launch_bounds__(1) void finalize_kernel(float* out) {
    const double LN2 = 0.69314718055994530942;
    out[0] = (float)((g_sum_log2 * LN2 - g_sum_out) /
                     ((double)B_ROWS * (double)N_COLS));
}

extern "C" void kernel_launch(void* const* d_in, const int* in_sizes, int n_in,
                              void* d_out, int out_size) {
    const float* outputs = (const float*)d_in[0];
    const int*   labels  = (const int*)d_in[1];
    float* out = (float*)d_out;

    init_kernel<<<1, 1>>>();
    listmle_kernel<<<B_ROWS, THREADS>>>(outputs, labels);
    finalize_kernel<<<1, 1>>>(out);
}